// round 9
// baseline (speedup 1.0000x reference)
#include <cuda_runtime.h>
#include <cuda_bf16.h>
#include <math.h>

// Problem shapes (fixed by the dataset)
#define B_  4096
#define L_  200
#define D_  256
#define BN_EPS 1e-5f

// -------- scratch (no allocations allowed) --------
__device__ float g_pp[2 * B_ * D_];          // 8 MB: per-half partial sums
__device__ float g_z[B_ * D_];               // 4 MB
__device__ float g_part[2 * 64 * D_];        // per-bm-tile col sums / sumsq
__device__ float g_lossp[256];               // per-block loss partials
__device__ unsigned int g_ticket;            // monotonic last-block ticket
__device__ unsigned int g_syncc[2];          // monotonic grid-sync counters

// float -> tf32 (round to nearest, bit pattern in u32)
__device__ __forceinline__ unsigned int f2tf32(float f)
{
    unsigned int u;
    asm("cvt.rna.tf32.f32 %0, %1;" : "=r"(u) : "f"(f));
    return u;
}

// emb load: non-coherent, L2 evict_last policy (keep table resident)
__device__ __forceinline__ float4 ldg_keep(const float4* p, unsigned long long pol)
{
    float4 v;
    asm volatile("ld.global.nc.L2::cache_hint.v4.f32 {%0,%1,%2,%3}, [%4], %5;"
                 : "=f"(v.x), "=f"(v.y), "=f"(v.z), "=f"(v.w)
                 : "l"(p), "l"(pol));
    return v;
}

__device__ __forceinline__ unsigned int ld_acq(unsigned int* p)
{
    unsigned int v;
    asm volatile("ld.acquire.gpu.u32 %0, [%1];" : "=r"(v) : "l"(p));
    return v;
}

// ============================================================
// Kernel 1: ragged gather partial-pool (unchanged from R8).
// ============================================================
__global__ void __launch_bounds__(64) pool_kernel(
    const int* __restrict__ tokens,
    const int* __restrict__ lengths,
    const float* __restrict__ emb)
{
    const int bid  = blockIdx.x;
    const int row  = bid >> 1;
    const int half = bid & 1;
    const int tid  = threadIdx.x;
    __shared__ int s_tok[104];

    unsigned long long pol;
    asm("createpolicy.fractional.L2::evict_last.b64 %0, 1.0;" : "=l"(pol));

    const int len   = lengths[row];
    const int n0    = len >> 1;
    const int start = half ? n0 : 0;
    const int cnt   = half ? (len - n0) : n0;

    for (int i = tid; i < cnt; i += 64)
        s_tok[i] = __ldcs(&tokens[row * L_ + start + i]);
    __syncthreads();

    const float4* __restrict__ emb4 = (const float4*)emb;  // row stride 64

    float4 a0 = make_float4(0.f, 0.f, 0.f, 0.f);
    float4 a1 = make_float4(0.f, 0.f, 0.f, 0.f);
    int l = 0;
    for (; l + 8 <= cnt; l += 8) {
        float4 v0 = ldg_keep(&emb4[(size_t)s_tok[l + 0] * 64 + tid], pol);
        float4 v1 = ldg_keep(&emb4[(size_t)s_tok[l + 1] * 64 + tid], pol);
        float4 v2 = ldg_keep(&emb4[(size_t)s_tok[l + 2] * 64 + tid], pol);
        float4 v3 = ldg_keep(&emb4[(size_t)s_tok[l + 3] * 64 + tid], pol);
        float4 v4 = ldg_keep(&emb4[(size_t)s_tok[l + 4] * 64 + tid], pol);
        float4 v5 = ldg_keep(&emb4[(size_t)s_tok[l + 5] * 64 + tid], pol);
        float4 v6 = ldg_keep(&emb4[(size_t)s_tok[l + 6] * 64 + tid], pol);
        float4 v7 = ldg_keep(&emb4[(size_t)s_tok[l + 7] * 64 + tid], pol);
        a0.x += (v0.x + v1.x) + (v2.x + v3.x);
        a0.y += (v0.y + v1.y) + (v2.y + v3.y);
        a0.z += (v0.z + v1.z) + (v2.z + v3.z);
        a0.w += (v0.w + v1.w) + (v2.w + v3.w);
        a1.x += (v4.x + v5.x) + (v6.x + v7.x);
        a1.y += (v4.y + v5.y) + (v6.y + v7.y);
        a1.z += (v4.z + v5.z) + (v6.z + v7.z);
        a1.w += (v4.w + v5.w) + (v6.w + v7.w);
    }
    for (; l < cnt; ++l) {
        float4 v = ldg_keep(&emb4[(size_t)s_tok[l] * 64 + tid], pol);
        a0.x += v.x; a0.y += v.y; a0.z += v.z; a0.w += v.w;
    }
    float4 o;
    o.x = a0.x + a1.x; o.y = a0.y + a1.y;
    o.z = a0.z + a1.z; o.w = a0.w + a1.w;
    __stcs(&((float4*)g_pp)[((size_t)half * B_ + row) * 64 + tid], o);
}

// ------------------------------------------------------------
// Monotonic grid barrier; acquire-load polling (no RED storm).
// All NB blocks co-resident (launch_bounds(256,3) => 444 slots).
// ------------------------------------------------------------
#define NB 256
__device__ __forceinline__ void gsync(int idx)
{
    __syncthreads();
    __threadfence();
    if (threadIdx.x == 0) {
        unsigned int my     = atomicAdd(&g_syncc[idx], 1u);
        unsigned int target = (my / NB + 1u) * NB;
        while (ld_acq(&g_syncc[idx]) < target)
            __nanosleep(64);
    }
    __syncthreads();
    __threadfence();
}

// ============================================================
// Kernel 2 (fused): tf32 GEMM + stats -> gsync -> head + loss.
// grid 256 x 256, 3 blocks/SM target (<=85 regs).
// Smem fragment layout is column-PERMUTED within each 8-group:
//   col' = (k&3)*2 + (k>>2)  => frag pairs {k, k+4} adjacent => LDS.64.
// ============================================================
__global__ void __launch_bounds__(256, 3) gemm_head_kernel(
    const int*   __restrict__ lengths,
    const float* __restrict__ W,
    const float* __restrict__ b1,
    const float* __restrict__ gamma,
    const float* __restrict__ beta,
    const float* __restrict__ w2,
    const float* __restrict__ b2,
    const float* __restrict__ t,
    float* __restrict__ Z,
    float* __restrict__ out)
{
    __shared__ union {
        struct {
            unsigned int As_u[64][68];
            unsigned int Bs_u[64][68];
            float s_inv[64];
        } g;
        struct {
            float s_g[D_], s_be[D_], s_w[D_];
            float red[8];
        } h;
    } sm;

    const int tid  = threadIdx.x;
    const int lane = tid & 31;
    const int warp = tid >> 5;
    const int bid  = blockIdx.x;

    // =================== Phase A: tf32 GEMM + stats ======================
    {
        const int g  = lane >> 2;
        const int tq = lane & 3;
        const int wm = warp >> 1;
        const int wn = warp & 1;
        const int bm = (bid >> 2) * 64;
        const int bn = (bid & 3) * 64;

        if (tid < 64) sm.g.s_inv[tid] = 1.f / (float)lengths[bm + tid];
        __syncthreads();

        const float4* __restrict__ pp4 = (const float4*)g_pp;

        float c[4][4] = {};

        for (int k0 = 0; k0 < D_; k0 += 64) {
            #pragma unroll
            for (int j = 0; j < 4; ++j) {
                int idx = tid + j * 256;
                int m   = idx >> 4;            // 0..63
                int k4  = idx & 15;            // float4-chunk 0..15
                int fi  = (k0 >> 2) + k4;
                // permuted base: chunk k4 covers cols 4k4..4k4+3 of the
                // 8-group (k4>>1)*8; even k4 -> slots {0,2,4,6}, odd -> {1,3,5,7}
                int base = (k4 >> 1) * 8 + (k4 & 1);
                {
                    float4 p0 = __ldcs(&pp4[(size_t)(bm + m) * 64 + fi]);
                    float4 p1 = __ldcs(&pp4[((size_t)B_ + bm + m) * 64 + fi]);
                    float inv = sm.g.s_inv[m];
                    sm.g.As_u[m][base + 0] = f2tf32((p0.x + p1.x) * inv);
                    sm.g.As_u[m][base + 2] = f2tf32((p0.y + p1.y) * inv);
                    sm.g.As_u[m][base + 4] = f2tf32((p0.z + p1.z) * inv);
                    sm.g.As_u[m][base + 6] = f2tf32((p0.w + p1.w) * inv);
                }
                {
                    float4 vb = *(const float4*)&W[(size_t)(bn + m) * D_ + k0 + k4 * 4];
                    sm.g.Bs_u[m][base + 0] = f2tf32(vb.x);
                    sm.g.Bs_u[m][base + 2] = f2tf32(vb.y);
                    sm.g.Bs_u[m][base + 4] = f2tf32(vb.z);
                    sm.g.Bs_u[m][base + 6] = f2tf32(vb.w);
                }
            }
            __syncthreads();

            const int am = wm * 16 + g;
            #pragma unroll
            for (int ks = 0; ks < 8; ++ks) {
                const int kc = ks * 8 + 2 * tq;   // permuted pair offset
                uint2 aA = *(const uint2*)&sm.g.As_u[am    ][kc]; // {k, k+4}
                uint2 aB = *(const uint2*)&sm.g.As_u[am + 8][kc];
                #pragma unroll
                for (int nb = 0; nb < 4; ++nb) {
                    const int bnrow = wn * 32 + nb * 8 + g;
                    uint2 bb = *(const uint2*)&sm.g.Bs_u[bnrow][kc];
                    asm volatile(
                        "mma.sync.aligned.m16n8k8.row.col.f32.tf32.tf32.f32 "
                        "{%0,%1,%2,%3}, {%4,%5,%6,%7}, {%8,%9}, {%0,%1,%2,%3};"
                        : "+f"(c[nb][0]), "+f"(c[nb][1]),
                          "+f"(c[nb][2]), "+f"(c[nb][3])
                        : "r"(aA.x), "r"(aB.x), "r"(aA.y), "r"(aB.y),
                          "r"(bb.x), "r"(bb.y));
                }
            }
            __syncthreads();
        }

        // epilogue: bias + Z store + fused stats
        const int row0 = bm + wm * 16 + g;
        float colsum[8], colsq[8];

        #pragma unroll
        for (int nb = 0; nb < 4; ++nb) {
            const int col = bn + wn * 32 + nb * 8 + 2 * tq;
            const float bz0 = b1[col], bz1 = b1[col + 1];
            float v00 = c[nb][0] + bz0, v01 = c[nb][1] + bz1;
            float v10 = c[nb][2] + bz0, v11 = c[nb][3] + bz1;
            *(float2*)&Z[(size_t)row0 * D_ + col]       = make_float2(v00, v01);
            *(float2*)&Z[(size_t)(row0 + 8) * D_ + col] = make_float2(v10, v11);
            colsum[nb * 2 + 0] = v00 + v10;
            colsum[nb * 2 + 1] = v01 + v11;
            colsq [nb * 2 + 0] = fmaf(v00, v00, v10 * v10);
            colsq [nb * 2 + 1] = fmaf(v01, v01, v11 * v11);
        }

        float* rs  = (float*)sm.g.As_u;   // [32][65]
        float* rss = (float*)sm.g.Bs_u;   // [32][65]
        const int contrib = wm * 8 + g;
        #pragma unroll
        for (int nb = 0; nb < 4; ++nb) {
            #pragma unroll
            for (int j = 0; j < 2; ++j) {
                int col = wn * 32 + nb * 8 + 2 * tq + j;
                rs [contrib * 65 + col] = colsum[nb * 2 + j];
                rss[contrib * 65 + col] = colsq [nb * 2 + j];
            }
        }
        __syncthreads();
        if (tid < 64) {
            float s = 0.f, ssq = 0.f;
            #pragma unroll 8
            for (int i = 0; i < 32; ++i) {
                s   += rs [i * 65 + tid];
                ssq += rss[i * 65 + tid];
            }
            g_part[(bid >> 2) * D_ + bn + tid]           = s;
            g_part[64 * D_ + (bid >> 2) * D_ + bn + tid] = ssq;
        }
    }

    gsync(0);

    // =================== Phase B: head (16 rows/block) ===================
    {
        float smv = 0.f, sq = 0.f;
        #pragma unroll 8
        for (int rb = 0; rb < 64; ++rb) {
            smv += g_part[rb * D_ + tid];
            sq  += g_part[64 * D_ + rb * D_ + tid];
        }
        float mu   = smv * (1.f / (float)B_);
        float var  = sq  * (1.f / (float)B_) - mu * mu;
        float rstd = rsqrtf(var + BN_EPS);
        float gg   = gamma[tid] * rstd;
        sm.h.s_g[tid]  = gg;
        sm.h.s_be[tid] = beta[tid] - gg * mu;
        sm.h.s_w[tid]  = w2[tid];
        __syncthreads();

        const int row0 = bid * 16 + warp * 2;
        const float b2v = b2[0];

        float acc[2] = {0.f, 0.f};
        #pragma unroll
        for (int k = 0; k < 8; ++k) {
            int dm = lane + 32 * k;
            float gk = sm.h.s_g[dm], bek = sm.h.s_be[dm], wk = sm.h.s_w[dm];
            #pragma unroll
            for (int r = 0; r < 2; ++r) {
                float zv = Z[(size_t)(row0 + r) * D_ + dm];
                acc[r] += fmaxf(fmaf(gk, zv, bek), 0.f) * wk;
            }
        }
        #pragma unroll
        for (int off = 16; off > 0; off >>= 1) {
            acc[0] += __shfl_xor_sync(0xFFFFFFFFu, acc[0], off);
            acc[1] += __shfl_xor_sync(0xFFFFFFFFu, acc[1], off);
        }

        if (lane == 0) {
            float lossacc = 0.f;
            #pragma unroll
            for (int r = 0; r < 2; ++r) {
                float l = acc[r] + b2v;
                out[1 + row0 + r] = l;
                float tb = t[row0 + r];
                lossacc += fmaxf(l, 0.f) - l * tb + log1pf(expf(-fabsf(l)));
            }
            sm.h.red[warp] = lossacc;
        }
        __syncthreads();

        __shared__ int s_last;
        if (tid == 0) {
            float sum = 0.f;
            #pragma unroll
            for (int w = 0; w < 8; ++w) sum += sm.h.red[w];
            g_lossp[bid] = sum;
            __threadfence();
            unsigned int my = atomicAdd(&g_ticket, 1u);
            s_last = ((my + 1u) & 255u) == 0u;
        }
        __syncthreads();

        if (s_last) {
            __threadfence();
            if (warp == 0) {
                float v = 0.f;
                #pragma unroll
                for (int j = 0; j < 8; ++j)
                    v += g_lossp[lane + 32 * j];
                #pragma unroll
                for (int off = 16; off > 0; off >>= 1)
                    v += __shfl_xor_sync(0xFFFFFFFFu, v, off);
                if (lane == 0) out[0] = v * (1.f / (float)B_);
            }
        }
    }
}

// ============================================================
// launch: 2 kernels, serial
// ============================================================
extern "C" void kernel_launch(void* const* d_in, const int* in_sizes, int n_in,
                              void* d_out, int out_size)
{
    const int*   tokens  = (const int*)d_in[0];
    const int*   lengths = (const int*)d_in[1];
    const float* t       = (const float*)d_in[2];
    const float* emb     = (const float*)d_in[3];
    const float* W1      = (const float*)d_in[4];
    const float* b1      = (const float*)d_in[5];
    const float* gamma   = (const float*)d_in[6];
    const float* beta    = (const float*)d_in[7];
    const float* w2      = (const float*)d_in[8];
    const float* b2      = (const float*)d_in[9];
    float* out = (float*)d_out;

    float* z; cudaGetSymbolAddress((void**)&z, g_z);

    pool_kernel<<<B_ * 2, 64>>>(tokens, lengths, emb);

    gemm_head_kernel<<<NB, 256>>>(lengths, W1, b1, gamma, beta, w2, b2, t,
                                  z, out);
}

// round 10
// speedup vs baseline: 1.0912x; 1.0912x over previous
#include <cuda_runtime.h>
#include <cuda_bf16.h>
#include <math.h>

// Problem shapes (fixed by the dataset)
#define B_  4096
#define L_  200
#define D_  256
#define BN_EPS 1e-5f

// -------- scratch (no allocations allowed) --------
__device__ float g_pp[2 * B_ * D_];          // 8 MB: per-half partial sums
__device__ float g_z[B_ * D_];               // 4 MB
__device__ float g_part[2 * 64 * D_];        // per-bm-tile col sums / sumsq
__device__ float g_lossp[256];               // per-block loss partials
__device__ unsigned int g_ticket;            // monotonic last-block ticket
__device__ unsigned int g_syncc[2];          // monotonic grid-sync counters

// float -> tf32 (round to nearest, bit pattern in u32)
__device__ __forceinline__ unsigned int f2tf32(float f)
{
    unsigned int u;
    asm("cvt.rna.tf32.f32 %0, %1;" : "=r"(u) : "f"(f));
    return u;
}

// emb load: non-coherent, L2 evict_last policy (keep table resident)
__device__ __forceinline__ float4 ldg_keep(const float4* p, unsigned long long pol)
{
    float4 v;
    asm volatile("ld.global.nc.L2::cache_hint.v4.f32 {%0,%1,%2,%3}, [%4], %5;"
                 : "=f"(v.x), "=f"(v.y), "=f"(v.z), "=f"(v.w)
                 : "l"(p), "l"(pol));
    return v;
}

// ============================================================
// Kernel 1: ragged gather partial-pool (unchanged, R8-proven).
// ============================================================
__global__ void __launch_bounds__(64) pool_kernel(
    const int* __restrict__ tokens,
    const int* __restrict__ lengths,
    const float* __restrict__ emb)
{
    const int bid  = blockIdx.x;
    const int row  = bid >> 1;
    const int half = bid & 1;
    const int tid  = threadIdx.x;
    __shared__ int s_tok[104];

    unsigned long long pol;
    asm("createpolicy.fractional.L2::evict_last.b64 %0, 1.0;" : "=l"(pol));

    const int len   = lengths[row];
    const int n0    = len >> 1;
    const int start = half ? n0 : 0;
    const int cnt   = half ? (len - n0) : n0;

    for (int i = tid; i < cnt; i += 64)
        s_tok[i] = __ldcs(&tokens[row * L_ + start + i]);
    __syncthreads();

    const float4* __restrict__ emb4 = (const float4*)emb;  // row stride 64

    float4 a0 = make_float4(0.f, 0.f, 0.f, 0.f);
    float4 a1 = make_float4(0.f, 0.f, 0.f, 0.f);
    int l = 0;
    for (; l + 8 <= cnt; l += 8) {
        float4 v0 = ldg_keep(&emb4[(size_t)s_tok[l + 0] * 64 + tid], pol);
        float4 v1 = ldg_keep(&emb4[(size_t)s_tok[l + 1] * 64 + tid], pol);
        float4 v2 = ldg_keep(&emb4[(size_t)s_tok[l + 2] * 64 + tid], pol);
        float4 v3 = ldg_keep(&emb4[(size_t)s_tok[l + 3] * 64 + tid], pol);
        float4 v4 = ldg_keep(&emb4[(size_t)s_tok[l + 4] * 64 + tid], pol);
        float4 v5 = ldg_keep(&emb4[(size_t)s_tok[l + 5] * 64 + tid], pol);
        float4 v6 = ldg_keep(&emb4[(size_t)s_tok[l + 6] * 64 + tid], pol);
        float4 v7 = ldg_keep(&emb4[(size_t)s_tok[l + 7] * 64 + tid], pol);
        a0.x += (v0.x + v1.x) + (v2.x + v3.x);
        a0.y += (v0.y + v1.y) + (v2.y + v3.y);
        a0.z += (v0.z + v1.z) + (v2.z + v3.z);
        a0.w += (v0.w + v1.w) + (v2.w + v3.w);
        a1.x += (v4.x + v5.x) + (v6.x + v7.x);
        a1.y += (v4.y + v5.y) + (v6.y + v7.y);
        a1.z += (v4.z + v5.z) + (v6.z + v7.z);
        a1.w += (v4.w + v5.w) + (v6.w + v7.w);
    }
    for (; l < cnt; ++l) {
        float4 v = ldg_keep(&emb4[(size_t)s_tok[l] * 64 + tid], pol);
        a0.x += v.x; a0.y += v.y; a0.z += v.z; a0.w += v.w;
    }
    float4 o;
    o.x = a0.x + a1.x; o.y = a0.y + a1.y;
    o.z = a0.z + a1.z; o.w = a0.w + a1.w;
    __stcs(&((float4*)g_pp)[((size_t)half * B_ + row) * 64 + tid], o);
}

// ------------------------------------------------------------
// Monotonic grid barrier (R8-proven form). Grid 256 blocks of 512
// threads, launch_bounds(512,2) => 296 slots => all co-resident.
// ------------------------------------------------------------
#define NB 256
__device__ __forceinline__ void gsync(int idx)
{
    __syncthreads();
    __threadfence();
    if (threadIdx.x == 0) {
        unsigned int my     = atomicAdd(&g_syncc[idx], 1u);
        unsigned int target = (my / NB + 1u) * NB;
        while (atomicAdd(&g_syncc[idx], 0u) < target)
            __nanosleep(64);
        __threadfence();
    }
    __syncthreads();
}

// ============================================================
// Kernel 2 (fused): tf32 GEMM (in-block split-K, 16 warps) + stats
// -> gsync -> head + ticketed loss.
// 512 threads: wm = warp&3 (m16), wn = (warp>>2)&1 (n32), kw = warp>>3.
// kw halves split the 8 ks-steps of each loaded chunk 4/4.
// ============================================================
__global__ void __launch_bounds__(512, 2) gemm_head_kernel(
    const int*   __restrict__ lengths,
    const float* __restrict__ W,
    const float* __restrict__ b1,
    const float* __restrict__ gamma,
    const float* __restrict__ beta,
    const float* __restrict__ w2,
    const float* __restrict__ b2,
    const float* __restrict__ t,
    float* __restrict__ Z,
    float* __restrict__ out)
{
    __shared__ union {
        struct {
            unsigned int As_u[64][68];   // 17408 B (also cbuf / rs)
            unsigned int Bs_u[64][68];   // 17408 B (also rss)
            float s_inv[64];
        } g;
        struct {
            float s_g[D_], s_be[D_], s_w[D_];
            float red[16];
        } h;
    } sm;

    const int tid  = threadIdx.x;
    const int lane = tid & 31;
    const int warp = tid >> 5;          // 0..15
    const int bid  = blockIdx.x;

    // =================== Phase A: tf32 GEMM + stats ======================
    {
        const int g  = lane >> 2;
        const int tq = lane & 3;
        const int wm = warp & 3;
        const int wn = (warp >> 2) & 1;
        const int kw = warp >> 3;       // 0/1: ks 0..3 or 4..7
        const int bm = (bid >> 2) * 64;
        const int bn = (bid & 3) * 64;

        if (tid < 64) sm.g.s_inv[tid] = 1.f / (float)lengths[bm + tid];
        __syncthreads();

        const float4* __restrict__ pp4 = (const float4*)g_pp;

        float c[4][4] = {};

        for (int k0 = 0; k0 < D_; k0 += 64) {
            #pragma unroll
            for (int j = 0; j < 2; ++j) {
                int idx = tid + j * 512;       // 0..1023
                int m   = idx >> 4;            // 0..63
                int k4  = idx & 15;            // 0..15
                int fi  = (k0 >> 2) + k4;
                float4 p0 = __ldcs(&pp4[(size_t)(bm + m) * 64 + fi]);
                float4 p1 = __ldcs(&pp4[((size_t)B_ + bm + m) * 64 + fi]);
                float inv = sm.g.s_inv[m];
                uint4 ua;
                ua.x = f2tf32((p0.x + p1.x) * inv);
                ua.y = f2tf32((p0.y + p1.y) * inv);
                ua.z = f2tf32((p0.z + p1.z) * inv);
                ua.w = f2tf32((p0.w + p1.w) * inv);
                *(uint4*)&sm.g.As_u[m][k4 * 4] = ua;
                float4 vb = *(const float4*)&W[(size_t)(bn + m) * D_ + k0 + k4 * 4];
                uint4 ub;
                ub.x = f2tf32(vb.x); ub.y = f2tf32(vb.y);
                ub.z = f2tf32(vb.z); ub.w = f2tf32(vb.w);
                *(uint4*)&sm.g.Bs_u[m][k4 * 4] = ub;
            }
            __syncthreads();

            const int am = wm * 16 + g;
            #pragma unroll
            for (int ks = 0; ks < 4; ++ks) {
                const int kc = (kw * 4 + ks) * 8;
                unsigned int a0 = sm.g.As_u[am    ][kc + tq];
                unsigned int a1 = sm.g.As_u[am + 8][kc + tq];
                unsigned int a2 = sm.g.As_u[am    ][kc + tq + 4];
                unsigned int a3 = sm.g.As_u[am + 8][kc + tq + 4];
                #pragma unroll
                for (int nb = 0; nb < 4; ++nb) {
                    const int bnrow = wn * 32 + nb * 8 + g;
                    unsigned int b0  = sm.g.Bs_u[bnrow][kc + tq];
                    unsigned int b1r = sm.g.Bs_u[bnrow][kc + tq + 4];
                    asm volatile(
                        "mma.sync.aligned.m16n8k8.row.col.f32.tf32.tf32.f32 "
                        "{%0,%1,%2,%3}, {%4,%5,%6,%7}, {%8,%9}, {%0,%1,%2,%3};"
                        : "+f"(c[nb][0]), "+f"(c[nb][1]),
                          "+f"(c[nb][2]), "+f"(c[nb][3])
                        : "r"(a0), "r"(a1), "r"(a2), "r"(a3),
                          "r"(b0), "r"(b1r));
                }
            }
            __syncthreads();
        }

        // ---- combine kw halves: kw=1 writes, kw=0 adds (stride 17) ----
        float* cbuf = (float*)sm.g.As_u;     // 8*32*17 = 4352 <= 4352 words
        if (kw == 1) {
            const int slot = ((warp - 8) * 32 + lane) * 17;
            #pragma unroll
            for (int nb = 0; nb < 4; ++nb)
                #pragma unroll
                for (int i = 0; i < 4; ++i)
                    cbuf[slot + nb * 4 + i] = c[nb][i];
        }
        __syncthreads();
        if (kw == 0) {
            const int slot = (warp * 32 + lane) * 17;
            #pragma unroll
            for (int nb = 0; nb < 4; ++nb)
                #pragma unroll
                for (int i = 0; i < 4; ++i)
                    c[nb][i] += cbuf[slot + nb * 4 + i];
        }
        __syncthreads();

        // ---- epilogue (kw=0 warps): bias + Z + stats to smem ----------
        float* rs  = (float*)sm.g.As_u;      // [32][65]
        float* rss = (float*)sm.g.Bs_u;      // [32][65]
        if (kw == 0) {
            const int row0 = bm + wm * 16 + g;
            const int contrib = wm * 8 + g;
            #pragma unroll
            for (int nb = 0; nb < 4; ++nb) {
                const int col = bn + wn * 32 + nb * 8 + 2 * tq;
                const float bz0 = b1[col], bz1 = b1[col + 1];
                float v00 = c[nb][0] + bz0, v01 = c[nb][1] + bz1;
                float v10 = c[nb][2] + bz0, v11 = c[nb][3] + bz1;
                *(float2*)&Z[(size_t)row0 * D_ + col]       = make_float2(v00, v01);
                *(float2*)&Z[(size_t)(row0 + 8) * D_ + col] = make_float2(v10, v11);
                int lc = wn * 32 + nb * 8 + 2 * tq;
                rs [contrib * 65 + lc]     = v00 + v10;
                rs [contrib * 65 + lc + 1] = v01 + v11;
                rss[contrib * 65 + lc]     = fmaf(v00, v00, v10 * v10);
                rss[contrib * 65 + lc + 1] = fmaf(v01, v01, v11 * v11);
            }
        }
        __syncthreads();
        if (tid < 64) {
            float s = 0.f, ssq = 0.f;
            #pragma unroll 8
            for (int i = 0; i < 32; ++i) {
                s   += rs [i * 65 + tid];
                ssq += rss[i * 65 + tid];
            }
            g_part[(bid >> 2) * D_ + bn + tid]           = s;
            g_part[64 * D_ + (bid >> 2) * D_ + bn + tid] = ssq;
        }
    }

    gsync(0);

    // =================== Phase B: head (16 rows, 1 row/warp) =============
    {
        if (tid < D_) {
            float smv = 0.f, sq = 0.f;
            #pragma unroll 8
            for (int rb = 0; rb < 64; ++rb) {
                smv += g_part[rb * D_ + tid];
                sq  += g_part[64 * D_ + rb * D_ + tid];
            }
            float mu   = smv * (1.f / (float)B_);
            float var  = sq  * (1.f / (float)B_) - mu * mu;
            float rstd = rsqrtf(var + BN_EPS);
            float gg   = gamma[tid] * rstd;
            sm.h.s_g[tid]  = gg;
            sm.h.s_be[tid] = beta[tid] - gg * mu;
            sm.h.s_w[tid]  = w2[tid];
        }
        __syncthreads();

        const int row = bid * 16 + warp;    // 1 row per warp
        const float b2v = b2[0];

        float acc = 0.f;
        #pragma unroll
        for (int k = 0; k < 8; ++k) {
            int dm = lane + 32 * k;
            float zv = Z[(size_t)row * D_ + dm];
            acc += fmaxf(fmaf(sm.h.s_g[dm], zv, sm.h.s_be[dm]), 0.f)
                   * sm.h.s_w[dm];
        }
        #pragma unroll
        for (int off = 16; off > 0; off >>= 1)
            acc += __shfl_xor_sync(0xFFFFFFFFu, acc, off);

        if (lane == 0) {
            float l = acc + b2v;
            out[1 + row] = l;
            float tb = t[row];
            sm.h.red[warp] =
                fmaxf(l, 0.f) - l * tb + log1pf(expf(-fabsf(l)));
        }
        __syncthreads();

        __shared__ int s_last;
        if (tid == 0) {
            float sum = 0.f;
            #pragma unroll
            for (int w = 0; w < 16; ++w) sum += sm.h.red[w];
            g_lossp[bid] = sum;
            __threadfence();
            unsigned int my = atomicAdd(&g_ticket, 1u);
            s_last = ((my + 1u) & 255u) == 0u;
        }
        __syncthreads();

        if (s_last) {
            __threadfence();
            if (warp == 0) {
                float v = 0.f;
                #pragma unroll
                for (int j = 0; j < 8; ++j)
                    v += g_lossp[lane + 32 * j];
                #pragma unroll
                for (int off = 16; off > 0; off >>= 1)
                    v += __shfl_xor_sync(0xFFFFFFFFu, v, off);
                if (lane == 0) out[0] = v * (1.f / (float)B_);
            }
        }
    }
}

// ============================================================
// launch: 2 kernels, serial
// ============================================================
extern "C" void kernel_launch(void* const* d_in, const int* in_sizes, int n_in,
                              void* d_out, int out_size)
{
    const int*   tokens  = (const int*)d_in[0];
    const int*   lengths = (const int*)d_in[1];
    const float* t       = (const float*)d_in[2];
    const float* emb     = (const float*)d_in[3];
    const float* W1      = (const float*)d_in[4];
    const float* b1      = (const float*)d_in[5];
    const float* gamma   = (const float*)d_in[6];
    const float* beta    = (const float*)d_in[7];
    const float* w2      = (const float*)d_in[8];
    const float* b2      = (const float*)d_in[9];
    float* out = (float*)d_out;

    float* z; cudaGetSymbolAddress((void**)&z, g_z);

    pool_kernel<<<B_ * 2, 64>>>(tokens, lengths, emb);

    gemm_head_kernel<<<NB, 512>>>(lengths, W1, b1, gamma, beta, w2, b2, t,
                                  z, out);
}